// round 3
// baseline (speedup 1.0000x reference)
#include <cuda_runtime.h>
#include <math.h>

// Problem dims
#define NN   81
#define NE   1620
#define IND  10
#define HID  8192
#define ACT  729

// Split-K segmentation for the two GEMVs (deterministic: no fp atomics)
#define NSEG1 64
#define ROWS1 (HID / NSEG1)   // 128
#define NSEG2 64
#define ROWS2 (HID / NSEG2)   // 128

// Static device scratch (no allocations allowed)
__device__ float d_y[NN * IND];          // A_norm @ x
__device__ float d_hn[NN * HID];         // per-node LN output
__device__ float d_p1[NSEG1 * HID];      // W1 GEMV partials
__device__ float d_p2[NSEG2 * ACT];      // W2 GEMV partials

__device__ __forceinline__ float warpSum(float v) {
    #pragma unroll
    for (int o = 16; o; o >>= 1) v += __shfl_xor_sync(0xFFFFFFFFu, v, o);
    return v;
}
__device__ __forceinline__ float warpMax(float v) {
    #pragma unroll
    for (int o = 16; o; o >>= 1) v = fmaxf(v, __shfl_xor_sync(0xFFFFFFFFu, v, o));
    return v;
}

// ---------------------------------------------------------------------------
// K0: graph aggregation y = A_norm @ x   (one block; tiny)
// Handles edge_index stored as either int64 or int32 (auto-detect).
// ---------------------------------------------------------------------------
__global__ void k0_aggregate(const float* __restrict__ x, const void* __restrict__ ei_raw) {
    __shared__ int   s_deg[NN];
    __shared__ float s_dinv[NN];
    __shared__ float s_y[NN * IND];
    __shared__ int   s_is64;

    int tid = threadIdx.x;
    int bd  = blockDim.x;

    if (tid == 0) s_is64 = 1;
    for (int i = tid; i < NN; i += bd) s_deg[i] = 0;
    for (int i = tid; i < NN * IND; i += bd) s_y[i] = 0.f;
    __syncthreads();

    // dtype detection: if int64, high words of first NE entries (values 0..80) are all 0
    const int* p32 = (const int*)ei_raw;
    for (int e = tid; e < NE; e += bd)
        if (p32[2 * e + 1] != 0) s_is64 = 0;   // benign race: only writes 0
    __syncthreads();
    const int is64 = s_is64;

    // degree (dst side); +1 for the self loop folded into the rsqrt below
    for (int e = tid; e < NE; e += bd) {
        int d = is64 ? p32[2 * (NE + e)] : p32[NE + e];
        atomicAdd(&s_deg[d], 1);
    }
    __syncthreads();
    for (int i = tid; i < NN; i += bd)
        s_dinv[i] = rsqrtf((float)s_deg[i] + 1.0f);
    __syncthreads();

    // edge messages
    for (int e = tid; e < NE; e += bd) {
        int s = is64 ? p32[2 * e]        : p32[e];
        int d = is64 ? p32[2 * (NE + e)] : p32[NE + e];
        float nrm = s_dinv[s] * s_dinv[d];
        #pragma unroll
        for (int k = 0; k < IND; k++)
            atomicAdd(&s_y[d * IND + k], nrm * x[s * IND + k]);
    }
    // self loops
    for (int i = tid; i < NN; i += bd) {
        float nrm = s_dinv[i] * s_dinv[i];
        #pragma unroll
        for (int k = 0; k < IND; k++)
            atomicAdd(&s_y[i * IND + k], nrm * x[i * IND + k]);
    }
    __syncthreads();
    for (int i = tid; i < NN * IND; i += bd) d_y[i] = s_y[i];
}

// ---------------------------------------------------------------------------
// K1: per-node  t = relu(y @ W_gcn + b), LayerNorm, store hn. 81 blocks x 256.
// ---------------------------------------------------------------------------
__global__ void k1_gcn_ln(const float* __restrict__ Wg, const float* __restrict__ bg,
                          const float* __restrict__ lng, const float* __restrict__ lnb) {
    __shared__ float s_t[HID];           // 32 KB
    __shared__ float s_yv[IND];
    __shared__ float s_rs[8], s_rq[8];
    __shared__ float s_mu, s_rstd;

    int node = blockIdx.x;
    int tid = threadIdx.x;
    int lane = tid & 31, wid = tid >> 5;

    if (tid < IND) s_yv[tid] = d_y[node * IND + tid];
    __syncthreads();

    float yr[IND];
    #pragma unroll
    for (int k = 0; k < IND; k++) yr[k] = s_yv[k];

    float sum = 0.f, sq = 0.f;
    for (int j = tid; j < HID; j += blockDim.x) {
        float t = bg[j];
        #pragma unroll
        for (int k = 0; k < IND; k++) t += yr[k] * Wg[k * HID + j];
        t = fmaxf(t, 0.f);
        s_t[j] = t;
        sum += t;
        sq  += t * t;
    }
    sum = warpSum(sum); sq = warpSum(sq);
    if (lane == 0) { s_rs[wid] = sum; s_rq[wid] = sq; }
    __syncthreads();
    if (tid == 0) {
        float S = 0.f, Q = 0.f;
        #pragma unroll
        for (int w = 0; w < 8; w++) { S += s_rs[w]; Q += s_rq[w]; }
        float mu = S / (float)HID;
        float var = Q / (float)HID - mu * mu;
        s_mu = mu;
        s_rstd = rsqrtf(var + 1e-5f);
    }
    __syncthreads();
    float mu = s_mu, rstd = s_rstd;
    for (int j = tid; j < HID; j += blockDim.x)
        d_hn[node * HID + j] = (s_t[j] - mu) * rstd * lng[j] + lnb[j];
}

// ---------------------------------------------------------------------------
// K2: fused pool + split-K GEMV vs W1 [HID x HID].
// grid = (16 col tiles, NSEG1 segs), 128 threads.
// Each block first pools its own 128-row slice of g from d_hn (L2-resident),
// then streams its [128 x 512] tile of W1 with float4 loads using two
// independent accumulator chains (MLP ~16) for DRAM latency cover.
// ---------------------------------------------------------------------------
__global__ void k2_gemv1(const float* __restrict__ W1) {
    __shared__ float sg[ROWS1];
    int tid = threadIdx.x;
    int ct  = blockIdx.x;
    int seg = blockIdx.y;
    int i0  = seg * ROWS1;

    // pool: g[i0+tid] = sum_n hn[n][i0+tid]
    {
        float s = 0.f;
        #pragma unroll 3
        for (int n = 0; n < NN; n++) s += d_hn[n * HID + i0 + tid];
        sg[tid] = s;
    }
    __syncthreads();

    int j = ct * 512 + tid * 4;
    const float4* Wp = reinterpret_cast<const float4*>(W1 + (size_t)i0 * HID + j);
    const size_t rstride = HID / 4;

    float ax0 = 0.f, ay0 = 0.f, az0 = 0.f, aw0 = 0.f;
    float ax1 = 0.f, ay1 = 0.f, az1 = 0.f, aw1 = 0.f;
    #pragma unroll 8
    for (int ii = 0; ii < ROWS1 / 2; ii++) {
        float g0 = sg[ii];
        float g1 = sg[ii + ROWS1 / 2];
        float4 w0 = Wp[(size_t)ii * rstride];
        float4 w1 = Wp[(size_t)(ii + ROWS1 / 2) * rstride];
        ax0 += g0 * w0.x; ay0 += g0 * w0.y; az0 += g0 * w0.z; aw0 += g0 * w0.w;
        ax1 += g1 * w1.x; ay1 += g1 * w1.y; az1 += g1 * w1.z; aw1 += g1 * w1.w;
    }
    float4 o = make_float4(ax0 + ax1, ay0 + ay1, az0 + az1, aw0 + aw1);
    *reinterpret_cast<float4*>(&d_p1[seg * HID + j]) = o;
}

// ---------------------------------------------------------------------------
// K3: fused relu-reduce + split-K GEMV vs W2 [HID x ACT].
// grid = NSEG2 blocks of 256 threads; block first reduces the 64 p1 partials
// for its 128-row segment (+b1, relu), then each thread covers 3 columns.
// ---------------------------------------------------------------------------
__global__ void k3_gemv2(const float* __restrict__ W2, const float* __restrict__ b1) {
    __shared__ float sr[ROWS2];
    int tid = threadIdx.x;
    int seg = blockIdx.x;
    int i0  = seg * ROWS2;

    if (tid < ROWS2) {
        float s = b1[i0 + tid];
        #pragma unroll 8
        for (int sg2 = 0; sg2 < NSEG1; sg2++) s += d_p1[sg2 * HID + i0 + tid];
        sr[tid] = fmaxf(s, 0.f);
    }
    __syncthreads();

    int c0 = tid, c1 = tid + 256, c2 = tid + 512;
    float a0 = 0.f, a1 = 0.f, a2 = 0.f;
    #pragma unroll 4
    for (int ii = 0; ii < ROWS2; ii++) {
        const float* row = W2 + (size_t)(i0 + ii) * ACT;
        float ri = sr[ii];
        a0 += ri * row[c0];
        a1 += ri * row[c1];
        if (c2 < ACT) a2 += ri * row[c2];
    }
    d_p2[seg * ACT + c0] = a0;
    d_p2[seg * ACT + c1] = a1;
    if (c2 < ACT) d_p2[seg * ACT + c2] = a2;
}

// ---------------------------------------------------------------------------
// K4: reduce partials + b2, log_softmax, write output. One block, 768 threads.
// ---------------------------------------------------------------------------
__global__ void k4_softmax(const float* __restrict__ b2, float* __restrict__ out) {
    __shared__ float s_part[32];
    int tid = threadIdx.x;
    int lane = tid & 31, wid = tid >> 5;
    const int NW = 768 / 32;   // 24 warps

    float l = -INFINITY;
    if (tid < ACT) {
        float s = b2[tid];
        #pragma unroll 8
        for (int seg = 0; seg < NSEG2; seg++) s += d_p2[seg * ACT + tid];
        l = s;
    }

    // block max
    float m = warpMax(l);
    if (lane == 0) s_part[wid] = m;
    __syncthreads();
    if (tid < 32) {
        float v = (tid < NW) ? s_part[tid] : -INFINITY;
        v = warpMax(v);
        if (tid == 0) s_part[0] = v;
    }
    __syncthreads();
    float M = s_part[0];
    __syncthreads();

    // block sum of exp
    float e = (tid < ACT) ? expf(l - M) : 0.f;
    float s = warpSum(e);
    if (lane == 0) s_part[wid] = s;
    __syncthreads();
    if (tid < 32) {
        float v = (tid < NW) ? s_part[tid] : 0.f;
        v = warpSum(v);
        if (tid == 0) s_part[0] = logf(v);
    }
    __syncthreads();
    float lse = s_part[0];

    if (tid < ACT) out[tid] = l - M - lse;
}

// ---------------------------------------------------------------------------
extern "C" void kernel_launch(void* const* d_in, const int* in_sizes, int n_in,
                              void* d_out, int out_size) {
    const float* x   = (const float*)d_in[0];
    const void*  ei  = d_in[1];               // int64 or int32, auto-detected
    const float* Wg  = (const float*)d_in[2];
    const float* bg  = (const float*)d_in[3];
    const float* lng = (const float*)d_in[4];
    const float* lnb = (const float*)d_in[5];
    const float* W1  = (const float*)d_in[6];
    const float* b1  = (const float*)d_in[7];
    const float* W2  = (const float*)d_in[8];
    const float* b2  = (const float*)d_in[9];
    float* out = (float*)d_out;

    k0_aggregate<<<1, 128>>>(x, ei);
    k1_gcn_ln<<<NN, 256>>>(Wg, bg, lng, lnb);
    dim3 g2(HID / 512, NSEG1);
    k2_gemv1<<<g2, 128>>>(W1);
    k3_gemv2<<<NSEG2, 256>>>(W2, b1);
    k4_softmax<<<1, 768>>>(b2, out);
}

// round 4
// speedup vs baseline: 1.6292x; 1.6292x over previous
#include <cuda_runtime.h>
#include <math.h>

// Problem dims
#define NN   81
#define NE   1620
#define IND  10
#define HID  8192
#define ACT  729

// Split-K segmentation (deterministic: no fp atomics)
#define NSEG1 64
#define ROWS1 (HID / NSEG1)   // 128
#define NSEG2 128
#define ROWS2 (HID / NSEG2)   // 64

// Static device scratch
__device__ float d_y[NN * IND];          // A_norm @ x
__device__ float d_hn[NN * HID];         // per-node LN output
__device__ float d_p1[NSEG1 * HID];      // W1 GEMV partials
__device__ float d_p2[NSEG2 * ACT];      // W2 GEMV partials

__device__ __forceinline__ float warpSum(float v) {
    #pragma unroll
    for (int o = 16; o; o >>= 1) v += __shfl_xor_sync(0xFFFFFFFFu, v, o);
    return v;
}
__device__ __forceinline__ float warpMax(float v) {
    #pragma unroll
    for (int o = 16; o; o >>= 1) v = fmaxf(v, __shfl_xor_sync(0xFFFFFFFFu, v, o));
    return v;
}

// ---------------------------------------------------------------------------
// K0: graph aggregation y = A_norm @ x (one block; tiny). int64/int32 detect.
// ---------------------------------------------------------------------------
__global__ void k0_aggregate(const float* __restrict__ x, const void* __restrict__ ei_raw) {
    __shared__ int   s_deg[NN];
    __shared__ float s_dinv[NN];
    __shared__ float s_y[NN * IND];
    __shared__ int   s_is64;

    int tid = threadIdx.x;
    int bd  = blockDim.x;

    if (tid == 0) s_is64 = 1;
    for (int i = tid; i < NN; i += bd) s_deg[i] = 0;
    for (int i = tid; i < NN * IND; i += bd) s_y[i] = 0.f;
    __syncthreads();

    const int* p32 = (const int*)ei_raw;
    for (int e = tid; e < NE; e += bd)
        if (p32[2 * e + 1] != 0) s_is64 = 0;   // benign race: only writes 0
    __syncthreads();
    const int is64 = s_is64;

    for (int e = tid; e < NE; e += bd) {
        int d = is64 ? p32[2 * (NE + e)] : p32[NE + e];
        atomicAdd(&s_deg[d], 1);
    }
    __syncthreads();
    for (int i = tid; i < NN; i += bd)
        s_dinv[i] = rsqrtf((float)s_deg[i] + 1.0f);
    __syncthreads();

    for (int e = tid; e < NE; e += bd) {
        int s = is64 ? p32[2 * e]        : p32[e];
        int d = is64 ? p32[2 * (NE + e)] : p32[NE + e];
        float nrm = s_dinv[s] * s_dinv[d];
        #pragma unroll
        for (int k = 0; k < IND; k++)
            atomicAdd(&s_y[d * IND + k], nrm * x[s * IND + k]);
    }
    for (int i = tid; i < NN; i += bd) {
        float nrm = s_dinv[i] * s_dinv[i];
        #pragma unroll
        for (int k = 0; k < IND; k++)
            atomicAdd(&s_y[i * IND + k], nrm * x[i * IND + k]);
    }
    __syncthreads();
    for (int i = tid; i < NN * IND; i += bd) d_y[i] = s_y[i];
}

// ---------------------------------------------------------------------------
// K1: per-node  t = relu(y @ W_gcn + b), LayerNorm, store hn. 81 blocks x 512.
// ---------------------------------------------------------------------------
__global__ void k1_gcn_ln(const float* __restrict__ Wg, const float* __restrict__ bg,
                          const float* __restrict__ lng, const float* __restrict__ lnb) {
    __shared__ float s_t[HID];           // 32 KB
    __shared__ float s_yv[IND];
    __shared__ float s_rs[16], s_rq[16];
    __shared__ float s_mu, s_rstd;

    int node = blockIdx.x;
    int tid = threadIdx.x;
    int lane = tid & 31, wid = tid >> 5;

    if (tid < IND) s_yv[tid] = d_y[node * IND + tid];
    __syncthreads();

    float yr[IND];
    #pragma unroll
    for (int k = 0; k < IND; k++) yr[k] = s_yv[k];

    float sum = 0.f, sq = 0.f;
    for (int j = tid; j < HID; j += blockDim.x) {
        float wv[IND];
        #pragma unroll
        for (int k = 0; k < IND; k++) wv[k] = __ldg(&Wg[k * HID + j]);
        float t = bg[j];
        #pragma unroll
        for (int k = 0; k < IND; k++) t += yr[k] * wv[k];
        t = fmaxf(t, 0.f);
        s_t[j] = t;
        sum += t;
        sq  += t * t;
    }
    sum = warpSum(sum); sq = warpSum(sq);
    if (lane == 0) { s_rs[wid] = sum; s_rq[wid] = sq; }
    __syncthreads();
    if (tid == 0) {
        float S = 0.f, Q = 0.f;
        #pragma unroll
        for (int w = 0; w < 16; w++) { S += s_rs[w]; Q += s_rq[w]; }
        float mu = S / (float)HID;
        float var = Q / (float)HID - mu * mu;
        s_mu = mu;
        s_rstd = rsqrtf(var + 1e-5f);
    }
    __syncthreads();
    float mu = s_mu, rstd = s_rstd;
    for (int j = tid; j < HID; j += blockDim.x)
        d_hn[node * HID + j] = (s_t[j] - mu) * rstd * lng[j] + lnb[j];
}

// ---------------------------------------------------------------------------
// K2: fused pool + split-K GEMV vs W1 [HID x HID].
// grid = (8 col tiles of 1024 cols, NSEG1=64 segs) = 512 blocks x 256 threads.
// Explicit 8-deep float4 load batching (__ldcs streaming) -> ~16 MB in flight.
// ---------------------------------------------------------------------------
__global__ void k2_gemv1(const float* __restrict__ W1) {
    __shared__ float sg[ROWS1];
    int tid = threadIdx.x;
    int ct  = blockIdx.x;
    int seg = blockIdx.y;
    int i0  = seg * ROWS1;

    if (tid < ROWS1) {
        float s = 0.f;
        #pragma unroll 3
        for (int n = 0; n < NN; n++) s += d_hn[n * HID + i0 + tid];
        sg[tid] = s;
    }
    __syncthreads();

    int j = ct * 1024 + tid * 4;
    const float4* Wp = reinterpret_cast<const float4*>(W1 + (size_t)i0 * HID + j);
    const size_t rstride = HID / 4;

    float4 acc0 = make_float4(0.f, 0.f, 0.f, 0.f);
    float4 acc1 = make_float4(0.f, 0.f, 0.f, 0.f);
    float4 acc2 = make_float4(0.f, 0.f, 0.f, 0.f);
    float4 acc3 = make_float4(0.f, 0.f, 0.f, 0.f);

    #pragma unroll 2
    for (int ii = 0; ii < ROWS1; ii += 8) {
        float4 w[8];
        #pragma unroll
        for (int k = 0; k < 8; k++)
            w[k] = __ldcs(&Wp[(size_t)(ii + k) * rstride]);
        float gv[8];
        #pragma unroll
        for (int k = 0; k < 8; k++) gv[k] = sg[ii + k];
        #pragma unroll
        for (int k = 0; k < 8; k++) {
            float4* a = (k & 3) == 0 ? &acc0 : (k & 3) == 1 ? &acc1 : (k & 3) == 2 ? &acc2 : &acc3;
            a->x += gv[k] * w[k].x;
            a->y += gv[k] * w[k].y;
            a->z += gv[k] * w[k].z;
            a->w += gv[k] * w[k].w;
        }
    }
    float4 o = make_float4(acc0.x + acc1.x + acc2.x + acc3.x,
                           acc0.y + acc1.y + acc2.y + acc3.y,
                           acc0.z + acc1.z + acc2.z + acc3.z,
                           acc0.w + acc1.w + acc2.w + acc3.w);
    *reinterpret_cast<float4*>(&d_p1[seg * HID + j]) = o;
}

// ---------------------------------------------------------------------------
// K3: fused relu-reduce + split-K GEMV vs W2 [HID x ACT].
// grid = (3 col groups, NSEG2=128 segs) = 384 blocks x 256 threads.
// Each block reduces p1 for its 64-row segment, then 8-deep batched loads.
// ---------------------------------------------------------------------------
__global__ void k3_gemv2(const float* __restrict__ W2, const float* __restrict__ b1) {
    __shared__ float sr[ROWS2];
    int tid = threadIdx.x;
    int cg  = blockIdx.x;
    int seg = blockIdx.y;
    int i0  = seg * ROWS2;

    if (tid < ROWS2) {
        float s = b1[i0 + tid];
        #pragma unroll 8
        for (int sg2 = 0; sg2 < NSEG1; sg2++) s += d_p1[sg2 * HID + i0 + tid];
        sr[tid] = fmaxf(s, 0.f);
    }
    __syncthreads();

    int c = cg * 256 + tid;
    bool valid = (c < ACT);
    int cl = valid ? c : (ACT - 1);
    const float* Wb = W2 + (size_t)i0 * ACT + cl;

    float a0 = 0.f, a1 = 0.f;
    #pragma unroll 2
    for (int ii = 0; ii < ROWS2; ii += 8) {
        float w[8];
        #pragma unroll
        for (int k = 0; k < 8; k++)
            w[k] = __ldg(&Wb[(size_t)(ii + k) * ACT]);
        #pragma unroll
        for (int k = 0; k < 8; k++) {
            float rv = sr[ii + k];
            if (k & 1) a1 += rv * w[k]; else a0 += rv * w[k];
        }
    }
    if (valid) d_p2[seg * ACT + c] = a0 + a1;
}

// ---------------------------------------------------------------------------
// K4: reduce partials + b2, log_softmax, write output. One block, 768 threads.
// ---------------------------------------------------------------------------
__global__ void k4_softmax(const float* __restrict__ b2, float* __restrict__ out) {
    __shared__ float s_part[32];
    int tid = threadIdx.x;
    int lane = tid & 31, wid = tid >> 5;
    const int NW = 768 / 32;   // 24 warps

    float l = -INFINITY;
    if (tid < ACT) {
        float s = b2[tid];
        #pragma unroll 8
        for (int seg = 0; seg < NSEG2; seg++) s += d_p2[seg * ACT + tid];
        l = s;
    }

    float m = warpMax(l);
    if (lane == 0) s_part[wid] = m;
    __syncthreads();
    if (tid < 32) {
        float v = (tid < NW) ? s_part[tid] : -INFINITY;
        v = warpMax(v);
        if (tid == 0) s_part[0] = v;
    }
    __syncthreads();
    float M = s_part[0];
    __syncthreads();

    float e = (tid < ACT) ? expf(l - M) : 0.f;
    float s = warpSum(e);
    if (lane == 0) s_part[wid] = s;
    __syncthreads();
    if (tid < 32) {
        float v = (tid < NW) ? s_part[tid] : 0.f;
        v = warpSum(v);
        if (tid == 0) s_part[0] = logf(v);
    }
    __syncthreads();
    float lse = s_part[0];

    if (tid < ACT) out[tid] = l - M - lse;
}

// ---------------------------------------------------------------------------
extern "C" void kernel_launch(void* const* d_in, const int* in_sizes, int n_in,
                              void* d_out, int out_size) {
    const float* x   = (const float*)d_in[0];
    const void*  ei  = d_in[1];               // int64 or int32, auto-detected
    const float* Wg  = (const float*)d_in[2];
    const float* bg  = (const float*)d_in[3];
    const float* lng = (const float*)d_in[4];
    const float* lnb = (const float*)d_in[5];
    const float* W1  = (const float*)d_in[6];
    const float* b1  = (const float*)d_in[7];
    const float* W2  = (const float*)d_in[8];
    const float* b2  = (const float*)d_in[9];
    float* out = (float*)d_out;

    k0_aggregate<<<1, 128>>>(x, ei);
    k1_gcn_ln<<<NN, 512>>>(Wg, bg, lng, lnb);
    dim3 g2(HID / 1024, NSEG1);
    k2_gemv1<<<g2, 256>>>(W1);
    dim3 g3(3, NSEG2);
    k3_gemv2<<<g3, 256>>>(W2, b1);
    k4_softmax<<<1, 768>>>(b2, out);
}

// round 5
// speedup vs baseline: 1.7688x; 1.0857x over previous
#include <cuda_runtime.h>
#include <math.h>

// Problem dims
#define NN   81
#define NE   1620
#define IND  10
#define HID  8192
#define ACT  729

// Split-K segmentation (deterministic: no fp atomics)
#define NSEG1 64
#define ROWS1 (HID / NSEG1)   // 128
#define NSEG2 128
#define ROWS2 (HID / NSEG2)   // 64

// Static device scratch
__device__ float d_y[NN * IND];          // A_norm @ x
__device__ float d_hn[NN * HID];         // per-node LN output
__device__ float d_g[HID];               // pooled graph vector
__device__ float d_p1[NSEG1 * HID];      // W1 GEMV partials
__device__ float d_r[HID];               // relu(g@W1+b1)
__device__ float d_p2[NSEG2 * ACT];      // W2 GEMV partials

__device__ __forceinline__ float warpSum(float v) {
    #pragma unroll
    for (int o = 16; o; o >>= 1) v += __shfl_xor_sync(0xFFFFFFFFu, v, o);
    return v;
}
__device__ __forceinline__ float warpMax(float v) {
    #pragma unroll
    for (int o = 16; o; o >>= 1) v = fmaxf(v, __shfl_xor_sync(0xFFFFFFFFu, v, o));
    return v;
}

// ---------------------------------------------------------------------------
// K0: graph aggregation y = A_norm @ x (one block; tiny). int64/int32 detect.
// ---------------------------------------------------------------------------
__global__ void k0_aggregate(const float* __restrict__ x, const void* __restrict__ ei_raw) {
    __shared__ int   s_deg[NN];
    __shared__ float s_dinv[NN];
    __shared__ float s_y[NN * IND];
    __shared__ int   s_is64;

    int tid = threadIdx.x;
    int bd  = blockDim.x;

    if (tid == 0) s_is64 = 1;
    for (int i = tid; i < NN; i += bd) s_deg[i] = 0;
    for (int i = tid; i < NN * IND; i += bd) s_y[i] = 0.f;
    __syncthreads();

    const int* p32 = (const int*)ei_raw;
    for (int e = tid; e < NE; e += bd)
        if (p32[2 * e + 1] != 0) s_is64 = 0;   // benign race: only writes 0
    __syncthreads();
    const int is64 = s_is64;

    for (int e = tid; e < NE; e += bd) {
        int d = is64 ? p32[2 * (NE + e)] : p32[NE + e];
        atomicAdd(&s_deg[d], 1);
    }
    __syncthreads();
    for (int i = tid; i < NN; i += bd)
        s_dinv[i] = rsqrtf((float)s_deg[i] + 1.0f);
    __syncthreads();

    for (int e = tid; e < NE; e += bd) {
        int s = is64 ? p32[2 * e]        : p32[e];
        int d = is64 ? p32[2 * (NE + e)] : p32[NE + e];
        float nrm = s_dinv[s] * s_dinv[d];
        #pragma unroll
        for (int k = 0; k < IND; k++)
            atomicAdd(&s_y[d * IND + k], nrm * x[s * IND + k]);
    }
    for (int i = tid; i < NN; i += bd) {
        float nrm = s_dinv[i] * s_dinv[i];
        #pragma unroll
        for (int k = 0; k < IND; k++)
            atomicAdd(&s_y[i * IND + k], nrm * x[i * IND + k]);
    }
    __syncthreads();
    for (int i = tid; i < NN * IND; i += bd) d_y[i] = s_y[i];
}

// ---------------------------------------------------------------------------
// K1: per-node  t = relu(y @ W_gcn + b), LayerNorm, store hn. 81 blocks x 512.
// ---------------------------------------------------------------------------
__global__ void k1_gcn_ln(const float* __restrict__ Wg, const float* __restrict__ bg,
                          const float* __restrict__ lng, const float* __restrict__ lnb) {
    __shared__ float s_t[HID];           // 32 KB
    __shared__ float s_yv[IND];
    __shared__ float s_rs[16], s_rq[16];
    __shared__ float s_mu, s_rstd;

    int node = blockIdx.x;
    int tid = threadIdx.x;
    int lane = tid & 31, wid = tid >> 5;

    if (tid < IND) s_yv[tid] = d_y[node * IND + tid];
    __syncthreads();

    float yr[IND];
    #pragma unroll
    for (int k = 0; k < IND; k++) yr[k] = s_yv[k];

    float sum = 0.f, sq = 0.f;
    for (int j = tid; j < HID; j += blockDim.x) {
        float wv[IND];
        #pragma unroll
        for (int k = 0; k < IND; k++) wv[k] = __ldg(&Wg[k * HID + j]);
        float t = bg[j];
        #pragma unroll
        for (int k = 0; k < IND; k++) t += yr[k] * wv[k];
        t = fmaxf(t, 0.f);
        s_t[j] = t;
        sum += t;
        sq  += t * t;
    }
    sum = warpSum(sum); sq = warpSum(sq);
    if (lane == 0) { s_rs[wid] = sum; s_rq[wid] = sq; }
    __syncthreads();
    if (tid == 0) {
        float S = 0.f, Q = 0.f;
        #pragma unroll
        for (int w = 0; w < 16; w++) { S += s_rs[w]; Q += s_rq[w]; }
        float mu = S / (float)HID;
        float var = Q / (float)HID - mu * mu;
        s_mu = mu;
        s_rstd = rsqrtf(var + 1e-5f);
    }
    __syncthreads();
    float mu = s_mu, rstd = s_rstd;
    for (int j = tid; j < HID; j += blockDim.x)
        d_hn[node * HID + j] = (s_t[j] - mu) * rstd * lng[j] + lnb[j];
}

// ---------------------------------------------------------------------------
// K1b: pool g[j] = sum_n hn[n][j].  32 blocks x 256; d_hn is L2-resident.
// 4 independent accumulator chains for MLP.
// ---------------------------------------------------------------------------
__global__ void k1b_pool() {
    int j = blockIdx.x * blockDim.x + threadIdx.x;
    float s0 = 0.f, s1 = 0.f, s2 = 0.f, s3 = 0.f;
    #pragma unroll
    for (int n = 0; n < 80; n += 4) {
        s0 += d_hn[(n + 0) * HID + j];
        s1 += d_hn[(n + 1) * HID + j];
        s2 += d_hn[(n + 2) * HID + j];
        s3 += d_hn[(n + 3) * HID + j];
    }
    s0 += d_hn[80 * HID + j];
    d_g[j] = (s0 + s1) + (s2 + s3);
}

// ---------------------------------------------------------------------------
// K2: split-K GEMV vs W1 [HID x HID].
// grid = (8 col tiles of 1024 cols, NSEG1=64 segs) = 512 blocks x 256 threads.
// Explicit 8-deep float4 load batching (__ldcs streaming), 4 acc chains.
// ---------------------------------------------------------------------------
__global__ void k2_gemv1(const float* __restrict__ W1) {
    __shared__ float sg[ROWS1];
    int tid = threadIdx.x;
    int ct  = blockIdx.x;
    int seg = blockIdx.y;
    int i0  = seg * ROWS1;

    if (tid < ROWS1) sg[tid] = d_g[i0 + tid];
    __syncthreads();

    int j = ct * 1024 + tid * 4;
    const float4* Wp = reinterpret_cast<const float4*>(W1 + (size_t)i0 * HID + j);
    const size_t rstride = HID / 4;

    float4 acc0 = make_float4(0.f, 0.f, 0.f, 0.f);
    float4 acc1 = make_float4(0.f, 0.f, 0.f, 0.f);
    float4 acc2 = make_float4(0.f, 0.f, 0.f, 0.f);
    float4 acc3 = make_float4(0.f, 0.f, 0.f, 0.f);

    #pragma unroll 2
    for (int ii = 0; ii < ROWS1; ii += 8) {
        float4 w[8];
        #pragma unroll
        for (int k = 0; k < 8; k++)
            w[k] = __ldcs(&Wp[(size_t)(ii + k) * rstride]);
        float gv[8];
        #pragma unroll
        for (int k = 0; k < 8; k++) gv[k] = sg[ii + k];
        #pragma unroll
        for (int k = 0; k < 8; k++) {
            float4* a = (k & 3) == 0 ? &acc0 : (k & 3) == 1 ? &acc1 : (k & 3) == 2 ? &acc2 : &acc3;
            a->x += gv[k] * w[k].x;
            a->y += gv[k] * w[k].y;
            a->z += gv[k] * w[k].z;
            a->w += gv[k] * w[k].w;
        }
    }
    float4 o = make_float4(acc0.x + acc1.x + acc2.x + acc3.x,
                           acc0.y + acc1.y + acc2.y + acc3.y,
                           acc0.z + acc1.z + acc2.z + acc3.z,
                           acc0.w + acc1.w + acc2.w + acc3.w);
    *reinterpret_cast<float4*>(&d_p1[seg * HID + j]) = o;
}

// ---------------------------------------------------------------------------
// K2b: r = relu(sum_seg p1 + b1).  32 blocks x 256; p1 is L2-resident.
// ---------------------------------------------------------------------------
__global__ void k2b_relu(const float* __restrict__ b1) {
    int j = blockIdx.x * blockDim.x + threadIdx.x;
    float s0 = 0.f, s1 = 0.f, s2 = 0.f, s3 = 0.f;
    #pragma unroll
    for (int seg = 0; seg < NSEG1; seg += 4) {
        s0 += d_p1[(seg + 0) * HID + j];
        s1 += d_p1[(seg + 1) * HID + j];
        s2 += d_p1[(seg + 2) * HID + j];
        s3 += d_p1[(seg + 3) * HID + j];
    }
    d_r[j] = fmaxf(b1[j] + (s0 + s1) + (s2 + s3), 0.f);
}

// ---------------------------------------------------------------------------
// K3: split-K GEMV vs W2 [HID x ACT].
// grid = (6 col groups, NSEG2=128 segs) = 768 blocks x 128 threads.
// Depth-16 load batches, 4 accumulator chains. ~6.3 MB chip-wide in flight.
// ---------------------------------------------------------------------------
__global__ void k3_gemv2(const float* __restrict__ W2) {
    __shared__ float sr[ROWS2];
    int tid = threadIdx.x;
    int cg  = blockIdx.x;
    int seg = blockIdx.y;
    int i0  = seg * ROWS2;

    if (tid < ROWS2) sr[tid] = d_r[i0 + tid];
    __syncthreads();

    int c = cg * 128 + tid;
    bool valid = (c < ACT);
    int cl = valid ? c : (ACT - 1);
    const float* Wb = W2 + (size_t)i0 * ACT + cl;

    float a0 = 0.f, a1 = 0.f, a2 = 0.f, a3 = 0.f;
    #pragma unroll
    for (int ii = 0; ii < ROWS2; ii += 16) {
        float w[16];
        #pragma unroll
        for (int k = 0; k < 16; k++)
            w[k] = __ldg(&Wb[(size_t)(ii + k) * ACT]);
        #pragma unroll
        for (int k = 0; k < 16; k++) {
            float rv = sr[ii + k];
            if ((k & 3) == 0) a0 += rv * w[k];
            else if ((k & 3) == 1) a1 += rv * w[k];
            else if ((k & 3) == 2) a2 += rv * w[k];
            else a3 += rv * w[k];
        }
    }
    if (valid) d_p2[seg * ACT + c] = (a0 + a1) + (a2 + a3);
}

// ---------------------------------------------------------------------------
// K4: reduce partials + b2, log_softmax, write output. One block, 768 threads.
// ---------------------------------------------------------------------------
__global__ void k4_softmax(const float* __restrict__ b2, float* __restrict__ out) {
    __shared__ float s_part[32];
    int tid = threadIdx.x;
    int lane = tid & 31, wid = tid >> 5;
    const int NW = 768 / 32;   // 24 warps

    float l = -INFINITY;
    if (tid < ACT) {
        float s0 = 0.f, s1 = 0.f, s2 = 0.f, s3 = 0.f;
        #pragma unroll
        for (int seg = 0; seg < NSEG2; seg += 4) {
            s0 += d_p2[(seg + 0) * ACT + tid];
            s1 += d_p2[(seg + 1) * ACT + tid];
            s2 += d_p2[(seg + 2) * ACT + tid];
            s3 += d_p2[(seg + 3) * ACT + tid];
        }
        l = b2[tid] + (s0 + s1) + (s2 + s3);
    }

    float m = warpMax(l);
    if (lane == 0) s_part[wid] = m;
    __syncthreads();
    if (tid < 32) {
        float v = (tid < NW) ? s_part[tid] : -INFINITY;
        v = warpMax(v);
        if (tid == 0) s_part[0] = v;
    }
    __syncthreads();
    float M = s_part[0];
    __syncthreads();

    float e = (tid < ACT) ? expf(l - M) : 0.f;
    float s = warpSum(e);
    if (lane == 0) s_part[wid] = s;
    __syncthreads();
    if (tid < 32) {
        float v = (tid < NW) ? s_part[tid] : 0.f;
        v = warpSum(v);
        if (tid == 0) s_part[0] = logf(v);
    }
    __syncthreads();
    float lse = s_part[0];

    if (tid < ACT) out[tid] = l - M - lse;
}

// ---------------------------------------------------------------------------
extern "C" void kernel_launch(void* const* d_in, const int* in_sizes, int n_in,
                              void* d_out, int out_size) {
    const float* x   = (const float*)d_in[0];
    const void*  ei  = d_in[1];               // int64 or int32, auto-detected
    const float* Wg  = (const float*)d_in[2];
    const float* bg  = (const float*)d_in[3];
    const float* lng = (const float*)d_in[4];
    const float* lnb = (const float*)d_in[5];
    const float* W1  = (const float*)d_in[6];
    const float* b1  = (const float*)d_in[7];
    const float* W2  = (const float*)d_in[8];
    const float* b2  = (const float*)d_in[9];
    float* out = (float*)d_out;

    k0_aggregate<<<1, 128>>>(x, ei);
    k1_gcn_ln<<<NN, 512>>>(Wg, bg, lng, lnb);
    k1b_pool<<<HID / 256, 256>>>();
    dim3 g2(HID / 1024, NSEG1);
    k2_gemv1<<<g2, 256>>>(W1);
    k2b_relu<<<HID / 256, 256>>>(b1);
    dim3 g3(6, NSEG2);
    k3_gemv2<<<g3, 128>>>(W2);
    k4_softmax<<<1, 768>>>(b2, out);
}